// round 1
// baseline (speedup 1.0000x reference)
#include <cuda_runtime.h>
#include <math.h>

#define BB 64
#define SS 512
#define HH 768
#define LL 9
#define BS (BB*SS)

// ---------------- scratch (no allocs allowed) ----------------
__device__ float g_logits[BS*LL];
__device__ float g_den[BB];
__device__ float g_num[BB];
__device__ int   g_tags[BS];

__device__ __forceinline__ float ex2f(float x){ float y; asm("ex2.approx.ftz.f32 %0,%1;" : "=f"(y) : "f"(x)); return y; }
__device__ __forceinline__ float lg2f(float x){ float y; asm("lg2.approx.ftz.f32 %0,%1;" : "=f"(y) : "f"(x)); return y; }

// ---------------- 1. logits = hidden @ W + b  (warp per row) ----------------
__global__ void gemm_kernel(const float* __restrict__ hidden,
                            const float* __restrict__ W,
                            const float* __restrict__ bvec) {
    __shared__ float w_s[HH*LL];
    __shared__ float b_s[LL];
    int tid = threadIdx.x;
    for (int i = tid; i < HH*LL; i += blockDim.x) w_s[i] = W[i];
    if (tid < LL) b_s[tid] = bvec[tid];
    __syncthreads();
    int warp = tid >> 5, ln = tid & 31;
    int row = blockIdx.x * 8 + warp;
    if (row >= BS) return;
    const float* hp = hidden + (size_t)row * HH;
    float acc[LL];
    #pragma unroll
    for (int l = 0; l < LL; l++) acc[l] = 0.f;
    #pragma unroll
    for (int k = 0; k < HH/32; k++) {
        float x = hp[k*32 + ln];
        int base = (k*32 + ln) * LL;   // lane stride 9 words -> conflict-free
        #pragma unroll
        for (int l = 0; l < LL; l++) acc[l] += x * w_s[base + l];
    }
    #pragma unroll
    for (int l = 0; l < LL; l++) {
        float v = acc[l];
        #pragma unroll
        for (int o = 16; o > 0; o >>= 1) v += __shfl_down_sync(0xffffffffu, v, o);
        if (ln == 0) g_logits[(size_t)row*LL + l] = v + b_s[l];
    }
}

// ---------------- 2. CRF forward: warp0 = viterbi(+backtrack), warp1 = lognorm ----------------
__global__ void crf_kernel(const int* __restrict__ mask,
                           const float* __restrict__ start_t,
                           const float* __restrict__ end_t,
                           const float* __restrict__ trans) {
    const float L2E = 1.4426950408889634f;
    const unsigned FULL = 0xffffffffu;
    int b = blockIdx.x;
    int tid = threadIdx.x;
    int w = tid >> 5;
    int j = tid & 31;
    bool lane9 = (j < LL);
    const float* gl = g_logits + (size_t)b * SS * LL;
    const int*   mp = mask + b * SS;

    __shared__ unsigned char bp_sh[SS][LL];
    __shared__ unsigned char m_sh[SS];

    if (w == 0) {
        // ---------- Viterbi ----------
        float trow[LL];
        #pragma unroll
        for (int i = 0; i < LL; i++) trow[i] = lane9 ? trans[i*LL + j] : 0.f;
        float vs = lane9 ? (start_t[j] + gl[j]) : -1e30f;
        float em_c = lane9 ? gl[LL + j] : 0.f;
        int   m_c  = mp[1];
        for (int t = 1; t < SS; t++) {
            float em_n = 0.f; int m_n = 0;
            if (t + 1 < SS) {                       // prefetch next step
                em_n = lane9 ? gl[(t+1)*LL + j] : 0.f;
                m_n  = mp[t+1];
            }
            float best = -1e30f; int bi = 0;
            #pragma unroll
            for (int i = 0; i < LL; i++) {
                float s = __shfl_sync(FULL, vs, i);
                float v = s + trow[i];
                if (v > best) { best = v; bi = i; } // first-max wins == jnp.argmax
            }
            float nxt = best + em_c;
            if (lane9) bp_sh[t][j] = (unsigned char)bi;
            if (j == 0) m_sh[t] = (unsigned char)(m_c != 0);
            if (m_c && lane9) vs = nxt;
            em_c = em_n; m_c = m_n;
        }
        float fin = lane9 ? (vs + end_t[j]) : -1e30f;
        float bl_best = -1e30f; int bl = 0;
        #pragma unroll
        for (int i = 0; i < LL; i++) {
            float v = __shfl_sync(FULL, fin, i);
            if (v > bl_best) { bl_best = v; bl = i; }
        }
        __syncwarp();
        if (j == 0) {
            int cur = bl;
            g_tags[b*SS + SS - 1] = cur;
            for (int t = SS - 1; t >= 1; t--) {
                if (m_sh[t]) cur = bp_sh[t][cur];
                g_tags[b*SS + t - 1] = cur;
            }
        }
    } else {
        // ---------- log-norm (log2 domain: everything pre-scaled by log2(e)) ----------
        float trow[LL];
        #pragma unroll
        for (int i = 0; i < LL; i++) trow[i] = lane9 ? trans[i*LL + j] * L2E : 0.f;
        float sc = lane9 ? (start_t[j] + gl[j]) * L2E : -1e30f;
        float em_c = lane9 ? gl[LL + j] * L2E : 0.f;
        int   m_c  = mp[1];
        for (int t = 1; t < SS; t++) {
            float em_n = 0.f; int m_n = 0;
            if (t + 1 < SS) {
                em_n = lane9 ? gl[(t+1)*LL + j] * L2E : 0.f;
                m_n  = mp[t+1];
            }
            float v[LL];
            #pragma unroll
            for (int i = 0; i < LL; i++) {
                float s = __shfl_sync(FULL, sc, i);
                v[i] = s + trow[i];
            }
            float m = fmaxf(fmaxf(fmaxf(v[0],v[1]), fmaxf(v[2],v[3])),
                            fmaxf(fmaxf(v[4],v[5]), fmaxf(v[6],v[7])));
            m = fmaxf(m, v[8]);
            float p = ((ex2f(v[0]-m) + ex2f(v[1]-m)) + (ex2f(v[2]-m) + ex2f(v[3]-m)))
                    + ((ex2f(v[4]-m) + ex2f(v[5]-m)) + (ex2f(v[6]-m) + ex2f(v[7]-m)))
                    + ex2f(v[8]-m);
            float nxt = m + lg2f(p) + em_c;
            if (m_c) sc = nxt;   // lanes>=9 get garbage, never read
            em_c = em_n; m_c = m_n;
        }
        float fin = lane9 ? (sc + end_t[j] * L2E) : -1e30f;
        float fv[LL];
        #pragma unroll
        for (int i = 0; i < LL; i++) fv[i] = __shfl_sync(FULL, fin, i);
        if (j == 0) {
            float m = fv[0];
            #pragma unroll
            for (int i = 1; i < LL; i++) m = fmaxf(m, fv[i]);
            float p = 0.f;
            #pragma unroll
            for (int i = 0; i < LL; i++) p += ex2f(fv[i] - m);
            g_den[b] = (m + lg2f(p)) / L2E;
        }
    }
}

// ---------------- 3. numerator (warp per batch, parallel over t) ----------------
__global__ void num_kernel(const int* __restrict__ mask,
                           const int* __restrict__ labels,
                           const float* __restrict__ start_t,
                           const float* __restrict__ end_t,
                           const float* __restrict__ trans) {
    int b = blockIdx.x, ln = threadIdx.x;
    const float* gl = g_logits + (size_t)b * SS * LL;
    const int* mp = mask + b * SS;
    const int* lp = labels + b * SS;
    float acc = 0.f; int cnt = 0;
    for (int t = ln; t < SS; t += 32) {
        int m = mp[t]; cnt += (m != 0);
        if (t >= 1 && m) {
            int tg = lp[t];   if (tg == -100) tg = 0;
            int tp = lp[t-1]; if (tp == -100) tp = 0;
            acc += gl[t*LL + tg] + trans[tp*LL + tg];
        }
    }
    #pragma unroll
    for (int o = 16; o > 0; o >>= 1) {
        acc += __shfl_down_sync(0xffffffffu, acc, o);
        cnt += __shfl_down_sync(0xffffffffu, cnt, o);
    }
    if (ln == 0) {
        int t0 = lp[0]; if (t0 == -100) t0 = 0;
        float first = start_t[t0] + gl[t0];
        int last = cnt - 1;
        int lt = lp[last]; if (lt == -100) lt = 0;
        g_num[b] = first + acc + end_t[lt];
    }
}

// ---------------- 4. loss ----------------
__global__ void loss_kernel(float* __restrict__ out) {
    __shared__ float sh[BB];
    int t = threadIdx.x;
    sh[t] = g_num[t] - g_den[t];
    __syncthreads();
    if (t == 0) {
        float s = 0.f;
        for (int i = 0; i < BB; i++) s += sh[i];
        out[0] = -s / (float)BB;
    }
}

// ---------------- 5. one-hot fake logits ----------------
__global__ void onehot_kernel(const int* __restrict__ mask, float* __restrict__ out) {
    int idx = blockIdx.x * blockDim.x + threadIdx.x;
    if (idx >= BS*LL) return;
    int pos = idx / LL;
    int l = idx - pos * LL;
    int m = mask[pos];
    int tg = g_tags[pos];
    out[1 + idx] = (m && l == tg) ? 1.f : 0.f;
}

extern "C" void kernel_launch(void* const* d_in, const int* in_sizes, int n_in,
                              void* d_out, int out_size) {
    const float* hidden = (const float*)d_in[0];
    const int*   mask   = (const int*)  d_in[1];
    const int*   labels = (const int*)  d_in[2];
    const float* W      = (const float*)d_in[3];
    const float* bvec   = (const float*)d_in[4];
    const float* st     = (const float*)d_in[5];
    const float* en     = (const float*)d_in[6];
    const float* tr     = (const float*)d_in[7];
    float* out = (float*)d_out;

    gemm_kernel<<<BS/8, 256>>>(hidden, W, bvec);
    crf_kernel<<<BB, 64>>>(mask, st, en, tr);
    num_kernel<<<BB, 32>>>(mask, labels, st, en, tr);
    loss_kernel<<<1, BB>>>(out);
    onehot_kernel<<<(BS*LL + 255)/256, 256>>>(mask, out);
}